// round 2
// baseline (speedup 1.0000x reference)
#include <cuda_runtime.h>
#include <cuda_bf16.h>

#define N_NODES_C 40000
#define N_EDGES_C 640000
#define DIM 128

// scratch: relu(x@W + b) [40000 x 128 f32], decoded edge indices, dtype flag
__device__ float g_h[N_NODES_C * DIM];
__device__ int   g_row[N_EDGES_C];
__device__ int   g_col[N_EDGES_C];
__device__ int   g_is64;

// ---------------------------------------------------------------------------
// Kernel 0a: detect edge_index dtype.
// Reads only the first 2*E 32-bit words (valid under BOTH interpretations:
// int32 buffer has exactly 2E words; int64 buffer has 4E words).
// If dtype is int64 (little-endian, values in [0, 40000)), every odd word of
// the first E int64s is 0. If int32, odd words are col/row values, mostly !=0.
// ---------------------------------------------------------------------------
__global__ void detect_dtype_kernel(const int* __restrict__ ei32) {
    __shared__ int any_nz;
    if (threadIdx.x == 0) any_nz = 0;
    __syncthreads();
    int local = 0;
    for (int i = blockIdx.x * blockDim.x + threadIdx.x; i < N_EDGES_C;
         i += gridDim.x * blockDim.x)
        local |= ei32[2 * i + 1];
    if (local) any_nz = 1;          // benign race: only ever writes 1
    __syncthreads();
    if (threadIdx.x == 0 && any_nz) atomicExch(&g_is64, 0);
    // g_is64 default handled by init kernel below
}

__global__ void init_flag_kernel() { g_is64 = 1; }

// ---------------------------------------------------------------------------
// Kernel 0b: decode edge indices into int32 row/col arrays.
// ---------------------------------------------------------------------------
__global__ void decode_edges_kernel(const int* __restrict__ ei32) {
    int i = blockIdx.x * blockDim.x + threadIdx.x;
    if (i >= N_EDGES_C) return;
    if (g_is64) {
        g_row[i] = ei32[2 * i];                     // low word of row[i]
        g_col[i] = ei32[2 * N_EDGES_C + 2 * i];     // low word of col[i]
    } else {
        g_row[i] = ei32[i];
        g_col[i] = ei32[N_EDGES_C + i];
    }
}

// ---------------------------------------------------------------------------
// Kernel 1: zero the output (scatter-max identity = 0 here, since relu >= 0)
// ---------------------------------------------------------------------------
__global__ void zero_out_kernel(float4* __restrict__ out, int n4) {
    int i = blockIdx.x * blockDim.x + threadIdx.x;
    if (i < n4) out[i] = make_float4(0.f, 0.f, 0.f, 0.f);
}

// ---------------------------------------------------------------------------
// Kernel 2: h = relu(x @ W + b)
// Block = 256 threads = 8 warps, 64 rows/block. Warp -> 8 rows, lane -> 4
// contiguous output cols. X tile in 32KB static smem; W streamed via __ldg
// (64KB, becomes L1-resident).
// ---------------------------------------------------------------------------
__global__ __launch_bounds__(256)
void gemm_bias_relu_kernel(const float* __restrict__ x,
                           const float* __restrict__ w,
                           const float* __restrict__ bias,
                           float* __restrict__ h) {
    __shared__ float Xs[64 * DIM];   // 32 KB

    const int tid  = threadIdx.x;
    const int row0 = blockIdx.x * 64;

    // Stage X tile: 64 rows x 128 = 2048 float4, 8 per thread
    const float4* xg = (const float4*)(x + (size_t)row0 * DIM);
    float4* xs4 = (float4*)Xs;
    #pragma unroll
    for (int i = 0; i < 8; i++)
        xs4[tid + i * 256] = xg[tid + i * 256];
    __syncthreads();

    const int warp = tid >> 5;
    const int lane = tid & 31;

    float acc[8][4];
    #pragma unroll
    for (int r = 0; r < 8; r++)
        #pragma unroll
        for (int j = 0; j < 4; j++) acc[r][j] = 0.f;

    const float* xrow = Xs + warp * 8 * DIM;
    const float4* wrow = (const float4*)w;   // w[k][n] row-major, 32 float4/row

    #pragma unroll 4
    for (int k = 0; k < DIM; k++) {
        float4 w4 = __ldg(&wrow[k * 32 + lane]);
        #pragma unroll
        for (int r = 0; r < 8; r++) {
            float xv = xrow[r * DIM + k];
            acc[r][0] = fmaf(xv, w4.x, acc[r][0]);
            acc[r][1] = fmaf(xv, w4.y, acc[r][1]);
            acc[r][2] = fmaf(xv, w4.z, acc[r][2]);
            acc[r][3] = fmaf(xv, w4.w, acc[r][3]);
        }
    }

    float4 b4 = __ldg(&((const float4*)bias)[lane]);
    #pragma unroll
    for (int r = 0; r < 8; r++) {
        int row = row0 + warp * 8 + r;
        float4 o;
        o.x = fmaxf(acc[r][0] + b4.x, 0.f);
        o.y = fmaxf(acc[r][1] + b4.y, 0.f);
        o.z = fmaxf(acc[r][2] + b4.z, 0.f);
        o.w = fmaxf(acc[r][3] + b4.w, 0.f);
        ((float4*)(h + (size_t)row * DIM))[lane] = o;
    }
}

// ---------------------------------------------------------------------------
// Kernel 3: per-edge scatter-max. One warp per edge; lane covers 4 feats.
// All values >= 0 (relu + zero init), so int-view atomicMax == float max.
// ---------------------------------------------------------------------------
__global__ __launch_bounds__(256)
void scatter_max_kernel(const float* __restrict__ h,
                        float* __restrict__ out) {
    int widx = (int)((blockIdx.x * (long long)blockDim.x + threadIdx.x) >> 5);
    int lane = threadIdx.x & 31;
    if (widx >= N_EDGES_C) return;

    int r = g_row[widx];   // dst segment
    int c = g_col[widx];   // src node (gather)

    float4 v = __ldg(&((const float4*)(h + (size_t)c * DIM))[lane]);
    int* o = (int*)(out + (size_t)r * DIM) + lane * 4;
    atomicMax(o + 0, __float_as_int(v.x));
    atomicMax(o + 1, __float_as_int(v.y));
    atomicMax(o + 2, __float_as_int(v.z));
    atomicMax(o + 3, __float_as_int(v.w));
}

// ---------------------------------------------------------------------------
extern "C" void kernel_launch(void* const* d_in, const int* in_sizes, int n_in,
                              void* d_out, int out_size) {
    const float* x    = (const float*)d_in[0];
    const int*   ei32 = (const int*)d_in[1];   // raw words; dtype detected on device
    const float* w    = (const float*)d_in[2];
    const float* bias = (const float*)d_in[3];
    float*       out  = (float*)d_out;

    float* h;
    cudaGetSymbolAddress((void**)&h, g_h);

    // 0) detect dtype + decode edges
    init_flag_kernel<<<1, 1>>>();
    detect_dtype_kernel<<<256, 256>>>(ei32);
    decode_edges_kernel<<<(N_EDGES_C + 255) / 256, 256>>>(ei32);

    // 1) zero output
    int n4 = out_size / 4;
    zero_out_kernel<<<(n4 + 255) / 256, 256>>>((float4*)out, n4);

    // 2) GEMM + bias + relu
    gemm_bias_relu_kernel<<<N_NODES_C / 64, 256>>>(x, w, bias, h);

    // 3) edge-parallel scatter-max (8 warps per block -> 8 edges per block)
    scatter_max_kernel<<<(N_EDGES_C + 7) / 8, 256>>>(h, out);
}

// round 3
// speedup vs baseline: 1.4628x; 1.4628x over previous
#include <cuda_runtime.h>
#include <cuda_bf16.h>

#define N_NODES_C 40000
#define N_EDGES_C 640000
#define DIM 128

// scratch
__device__ float g_h[N_NODES_C * DIM];       // relu(x@W+b)
__device__ int   g_row[N_EDGES_C];
__device__ int   g_col[N_EDGES_C];
__device__ int   g_scol[N_EDGES_C];          // cols bucketed by row
__device__ int   g_cnt[N_NODES_C];
__device__ int   g_offs[N_NODES_C + 1];
__device__ int   g_cursor[N_NODES_C];
__device__ int   g_is64;

// ---------------------------------------------------------------------------
// 0a: init flag + zero histogram counters
// ---------------------------------------------------------------------------
__global__ void init_kernel() {
    int i = blockIdx.x * blockDim.x + threadIdx.x;
    if (i == 0) g_is64 = 1;
    if (i < N_NODES_C) g_cnt[i] = 0;
}

// ---------------------------------------------------------------------------
// 0b: detect edge_index dtype (reads only first 2E words, valid either way).
// int64 little-endian with values < 2^31 -> all odd words zero.
// ---------------------------------------------------------------------------
__global__ void detect_dtype_kernel(const int* __restrict__ ei32) {
    int local = 0;
    for (int i = blockIdx.x * blockDim.x + threadIdx.x; i < N_EDGES_C;
         i += gridDim.x * blockDim.x)
        local |= ei32[2 * i + 1];
    if (local) g_is64 = 0;   // benign race: only ever writes 0
}

// ---------------------------------------------------------------------------
// 0c: decode edges + histogram rows
// ---------------------------------------------------------------------------
__global__ void decode_hist_kernel(const int* __restrict__ ei32) {
    int i = blockIdx.x * blockDim.x + threadIdx.x;
    if (i >= N_EDGES_C) return;
    int r, c;
    if (g_is64) {
        r = ei32[2 * i];
        c = ei32[2 * N_EDGES_C + 2 * i];
    } else {
        r = ei32[i];
        c = ei32[N_EDGES_C + i];
    }
    g_row[i] = r;
    g_col[i] = c;
    atomicAdd(&g_cnt[r], 1);
}

// ---------------------------------------------------------------------------
// 0d: exclusive scan of counts -> offs, and init cursor. One block, 1024 thr.
// ---------------------------------------------------------------------------
__global__ __launch_bounds__(1024)
void scan_kernel() {
    __shared__ int sums[1024];
    const int t = threadIdx.x;
    const int CH = (N_NODES_C + 1023) / 1024;   // 40
    const int beg = t * CH;
    const int end = min(beg + CH, N_NODES_C);

    int s = 0;
    for (int i = beg; i < end; i++) s += g_cnt[i];
    sums[t] = s;
    __syncthreads();

    // Hillis-Steele inclusive scan
    for (int off = 1; off < 1024; off <<= 1) {
        int v = (t >= off) ? sums[t - off] : 0;
        __syncthreads();
        sums[t] += v;
        __syncthreads();
    }

    int running = sums[t] - s;   // exclusive prefix for this chunk
    for (int i = beg; i < end; i++) {
        g_offs[i]   = running;
        g_cursor[i] = running;
        running += g_cnt[i];
    }
    if (t == 1023) g_offs[N_NODES_C] = sums[1023];
}

// ---------------------------------------------------------------------------
// 0e: bucket cols by destination row
// ---------------------------------------------------------------------------
__global__ void bucket_kernel() {
    int i = blockIdx.x * blockDim.x + threadIdx.x;
    if (i >= N_EDGES_C) return;
    int r = g_row[i];
    int p = atomicAdd(&g_cursor[r], 1);
    g_scol[p] = g_col[i];
}

// ---------------------------------------------------------------------------
// 1: h = relu(x @ W + b). Block = 8 warps -> 64 rows; warp -> 8 rows,
//    lane -> 4 contiguous cols. X tile in smem, W streamed via L1.
// ---------------------------------------------------------------------------
__global__ __launch_bounds__(256)
void gemm_bias_relu_kernel(const float* __restrict__ x,
                           const float* __restrict__ w,
                           const float* __restrict__ bias,
                           float* __restrict__ h) {
    __shared__ float Xs[64 * DIM];   // 32 KB

    const int tid  = threadIdx.x;
    const int row0 = blockIdx.x * 64;

    const float4* xg = (const float4*)(x + (size_t)row0 * DIM);
    float4* xs4 = (float4*)Xs;
    #pragma unroll
    for (int i = 0; i < 8; i++)
        xs4[tid + i * 256] = xg[tid + i * 256];
    __syncthreads();

    const int warp = tid >> 5;
    const int lane = tid & 31;

    float acc[8][4];
    #pragma unroll
    for (int r = 0; r < 8; r++)
        #pragma unroll
        for (int j = 0; j < 4; j++) acc[r][j] = 0.f;

    const float* xrow = Xs + warp * 8 * DIM;
    const float4* wrow = (const float4*)w;

    #pragma unroll 4
    for (int k = 0; k < DIM; k++) {
        float4 w4 = __ldg(&wrow[k * 32 + lane]);
        #pragma unroll
        for (int r = 0; r < 8; r++) {
            float xv = xrow[r * DIM + k];
            acc[r][0] = fmaf(xv, w4.x, acc[r][0]);
            acc[r][1] = fmaf(xv, w4.y, acc[r][1]);
            acc[r][2] = fmaf(xv, w4.z, acc[r][2]);
            acc[r][3] = fmaf(xv, w4.w, acc[r][3]);
        }
    }

    float4 b4 = __ldg(&((const float4*)bias)[lane]);
    #pragma unroll
    for (int r = 0; r < 8; r++) {
        int row = row0 + warp * 8 + r;
        float4 o;
        o.x = fmaxf(acc[r][0] + b4.x, 0.f);
        o.y = fmaxf(acc[r][1] + b4.y, 0.f);
        o.z = fmaxf(acc[r][2] + b4.z, 0.f);
        o.w = fmaxf(acc[r][3] + b4.w, 0.f);
        ((float4*)(h + (size_t)row * DIM))[lane] = o;
    }
}

// ---------------------------------------------------------------------------
// 2: aggregate. One warp per node; lane covers 4 feats. Cols staged 32 at a
//    time via shfl so the h-gathers are independent (high MLP).
// ---------------------------------------------------------------------------
__global__ __launch_bounds__(256)
void aggregate_kernel(const float* __restrict__ h,
                      float* __restrict__ out) {
    int node = (int)((blockIdx.x * (long long)blockDim.x + threadIdx.x) >> 5);
    int lane = threadIdx.x & 31;
    if (node >= N_NODES_C) return;

    int beg = g_offs[node];
    int end = g_offs[node + 1];

    float4 acc = make_float4(0.f, 0.f, 0.f, 0.f);

    for (int base = beg; base < end; base += 32) {
        int myc = (base + lane < end) ? g_scol[base + lane] : 0;
        int cnt = min(32, end - base);
        #pragma unroll 4
        for (int j = 0; j < cnt; j++) {
            int c = __shfl_sync(0xFFFFFFFFu, myc, j);
            float4 v = __ldg(&((const float4*)(h + (size_t)c * DIM))[lane]);
            acc.x = fmaxf(acc.x, v.x);
            acc.y = fmaxf(acc.y, v.y);
            acc.z = fmaxf(acc.z, v.z);
            acc.w = fmaxf(acc.w, v.w);
        }
    }

    ((float4*)(out + (size_t)node * DIM))[lane] = acc;
}

// ---------------------------------------------------------------------------
extern "C" void kernel_launch(void* const* d_in, const int* in_sizes, int n_in,
                              void* d_out, int out_size) {
    const float* x    = (const float*)d_in[0];
    const int*   ei32 = (const int*)d_in[1];
    const float* w    = (const float*)d_in[2];
    const float* bias = (const float*)d_in[3];
    float*       out  = (float*)d_out;

    float* h;
    cudaGetSymbolAddress((void**)&h, g_h);

    init_kernel<<<(N_NODES_C + 255) / 256, 256>>>();
    detect_dtype_kernel<<<256, 256>>>(ei32);
    decode_hist_kernel<<<(N_EDGES_C + 255) / 256, 256>>>(ei32);
    scan_kernel<<<1, 1024>>>();
    bucket_kernel<<<(N_EDGES_C + 255) / 256, 256>>>();

    gemm_bias_relu_kernel<<<N_NODES_C / 64, 256>>>(x, w, bias, h);

    aggregate_kernel<<<(N_NODES_C * 32 + 255) / 256, 256>>>(h, out);
}

// round 4
// speedup vs baseline: 2.4102x; 1.6476x over previous
#include <cuda_runtime.h>
#include <cuda_bf16.h>

#define N_NODES_C 40000
#define N_EDGES_C 640000
#define DIM 128
#define SCAN_BLOCKS ((N_NODES_C + 255) / 256)   // 157

// scratch
__device__ float g_h[N_NODES_C * DIM];       // relu(x@W+b)
__device__ int   g_row[N_EDGES_C];
__device__ int   g_col[N_EDGES_C];
__device__ int   g_scol[N_EDGES_C];          // cols bucketed by row
__device__ int   g_cnt[N_NODES_C];
__device__ int   g_offs[N_NODES_C + 1];
__device__ int   g_cursor[N_NODES_C];
__device__ int   g_blksum[SCAN_BLOCKS];
__device__ int   g_blkoff[SCAN_BLOCKS];
__device__ int   g_is64;

// ---------------------------------------------------------------------------
// 0a: init flag + zero histogram counters
// ---------------------------------------------------------------------------
__global__ void init_kernel() {
    int i = blockIdx.x * blockDim.x + threadIdx.x;
    if (i == 0) g_is64 = 1;
    if (i < N_NODES_C) g_cnt[i] = 0;
}

// ---------------------------------------------------------------------------
// 0b: detect edge_index dtype (reads only first 2E words, valid either way).
// int64 little-endian with values < 2^31 -> all odd words zero.
// ---------------------------------------------------------------------------
__global__ void detect_dtype_kernel(const int* __restrict__ ei32) {
    int local = 0;
    for (int i = blockIdx.x * blockDim.x + threadIdx.x; i < N_EDGES_C;
         i += gridDim.x * blockDim.x)
        local |= ei32[2 * i + 1];
    if (local) g_is64 = 0;   // benign race: only ever writes 0
}

// ---------------------------------------------------------------------------
// 0c: decode edges + histogram rows
// ---------------------------------------------------------------------------
__global__ void decode_hist_kernel(const int* __restrict__ ei32) {
    int i = blockIdx.x * blockDim.x + threadIdx.x;
    if (i >= N_EDGES_C) return;
    int r, c;
    if (g_is64) {
        r = ei32[2 * i];
        c = ei32[2 * N_EDGES_C + 2 * i];
    } else {
        r = ei32[i];
        c = ei32[N_EDGES_C + i];
    }
    g_row[i] = r;
    g_col[i] = c;
    atomicAdd(&g_cnt[r], 1);
}

// ---------------------------------------------------------------------------
// 0d: three-phase parallel exclusive scan of g_cnt -> g_offs / g_cursor
// ---------------------------------------------------------------------------
__global__ __launch_bounds__(256)
void scan_blocksum_kernel() {
    __shared__ int sd[256];
    int i = blockIdx.x * 256 + threadIdx.x;
    sd[threadIdx.x] = (i < N_NODES_C) ? g_cnt[i] : 0;
    __syncthreads();
    #pragma unroll
    for (int s = 128; s > 0; s >>= 1) {
        if (threadIdx.x < s) sd[threadIdx.x] += sd[threadIdx.x + s];
        __syncthreads();
    }
    if (threadIdx.x == 0) g_blksum[blockIdx.x] = sd[0];
}

__global__ __launch_bounds__(256)
void scan_toplevel_kernel() {
    __shared__ int sd[256];
    int t = threadIdx.x;
    sd[t] = (t < SCAN_BLOCKS) ? g_blksum[t] : 0;
    __syncthreads();
    #pragma unroll
    for (int off = 1; off < 256; off <<= 1) {
        int v = (t >= off) ? sd[t - off] : 0;
        __syncthreads();
        sd[t] += v;
        __syncthreads();
    }
    if (t < SCAN_BLOCKS) g_blkoff[t] = sd[t] - g_blksum[t];  // exclusive
}

__global__ __launch_bounds__(256)
void scan_write_kernel() {
    __shared__ int sd[256];
    int t = threadIdx.x;
    int i = blockIdx.x * 256 + t;
    int v = (i < N_NODES_C) ? g_cnt[i] : 0;
    sd[t] = v;
    __syncthreads();
    #pragma unroll
    for (int off = 1; off < 256; off <<= 1) {
        int u = (t >= off) ? sd[t - off] : 0;
        __syncthreads();
        sd[t] += u;
        __syncthreads();
    }
    if (i < N_NODES_C) {
        int excl = g_blkoff[blockIdx.x] + sd[t] - v;
        g_offs[i]   = excl;
        g_cursor[i] = excl;
    }
    if (i == 0) g_offs[N_NODES_C] = N_EDGES_C;   // total is fixed
}

// ---------------------------------------------------------------------------
// 0e: bucket cols by destination row
// ---------------------------------------------------------------------------
__global__ void bucket_kernel() {
    int i = blockIdx.x * blockDim.x + threadIdx.x;
    if (i >= N_EDGES_C) return;
    int r = g_row[i];
    int p = atomicAdd(&g_cursor[r], 1);
    g_scol[p] = g_col[i];
}

// ---------------------------------------------------------------------------
// 1: h = relu(x @ W + b). Block = 8 warps -> 64 rows; warp -> 8 rows,
//    lane -> 4 contiguous cols. X tile in smem, W streamed via L1.
// ---------------------------------------------------------------------------
__global__ __launch_bounds__(256)
void gemm_bias_relu_kernel(const float* __restrict__ x,
                           const float* __restrict__ w,
                           const float* __restrict__ bias,
                           float* __restrict__ h) {
    __shared__ float Xs[64 * DIM];   // 32 KB

    const int tid  = threadIdx.x;
    const int row0 = blockIdx.x * 64;

    const float4* xg = (const float4*)(x + (size_t)row0 * DIM);
    float4* xs4 = (float4*)Xs;
    #pragma unroll
    for (int i = 0; i < 8; i++)
        xs4[tid + i * 256] = xg[tid + i * 256];
    __syncthreads();

    const int warp = tid >> 5;
    const int lane = tid & 31;

    float acc[8][4];
    #pragma unroll
    for (int r = 0; r < 8; r++)
        #pragma unroll
        for (int j = 0; j < 4; j++) acc[r][j] = 0.f;

    const float* xrow = Xs + warp * 8 * DIM;
    const float4* wrow = (const float4*)w;

    #pragma unroll 4
    for (int k = 0; k < DIM; k++) {
        float4 w4 = __ldg(&wrow[k * 32 + lane]);
        #pragma unroll
        for (int r = 0; r < 8; r++) {
            float xv = xrow[r * DIM + k];
            acc[r][0] = fmaf(xv, w4.x, acc[r][0]);
            acc[r][1] = fmaf(xv, w4.y, acc[r][1]);
            acc[r][2] = fmaf(xv, w4.z, acc[r][2]);
            acc[r][3] = fmaf(xv, w4.w, acc[r][3]);
        }
    }

    float4 b4 = __ldg(&((const float4*)bias)[lane]);
    #pragma unroll
    for (int r = 0; r < 8; r++) {
        int row = row0 + warp * 8 + r;
        float4 o;
        o.x = fmaxf(acc[r][0] + b4.x, 0.f);
        o.y = fmaxf(acc[r][1] + b4.y, 0.f);
        o.z = fmaxf(acc[r][2] + b4.z, 0.f);
        o.w = fmaxf(acc[r][3] + b4.w, 0.f);
        ((float4*)(h + (size_t)row * DIM))[lane] = o;
    }
}

// ---------------------------------------------------------------------------
// 2: aggregate. One warp per node; lane covers 4 feats. Cols staged 32 at a
//    time via shfl so the h-gathers are independent (high MLP).
// ---------------------------------------------------------------------------
__global__ __launch_bounds__(256)
void aggregate_kernel(const float* __restrict__ h,
                      float* __restrict__ out) {
    int node = (int)((blockIdx.x * (long long)blockDim.x + threadIdx.x) >> 5);
    int lane = threadIdx.x & 31;
    if (node >= N_NODES_C) return;

    int beg = g_offs[node];
    int end = g_offs[node + 1];

    float4 acc = make_float4(0.f, 0.f, 0.f, 0.f);

    for (int base = beg; base < end; base += 32) {
        int myc = (base + lane < end) ? g_scol[base + lane] : 0;
        int cnt = min(32, end - base);
        #pragma unroll 4
        for (int j = 0; j < cnt; j++) {
            int c = __shfl_sync(0xFFFFFFFFu, myc, j);
            float4 v = __ldg(&((const float4*)(h + (size_t)c * DIM))[lane]);
            acc.x = fmaxf(acc.x, v.x);
            acc.y = fmaxf(acc.y, v.y);
            acc.z = fmaxf(acc.z, v.z);
            acc.w = fmaxf(acc.w, v.w);
        }
    }

    ((float4*)(out + (size_t)node * DIM))[lane] = acc;
}

// ---------------------------------------------------------------------------
extern "C" void kernel_launch(void* const* d_in, const int* in_sizes, int n_in,
                              void* d_out, int out_size) {
    const float* x    = (const float*)d_in[0];
    const int*   ei32 = (const int*)d_in[1];
    const float* w    = (const float*)d_in[2];
    const float* bias = (const float*)d_in[3];
    float*       out  = (float*)d_out;

    float* h;
    cudaGetSymbolAddress((void**)&h, g_h);

    init_kernel<<<(N_NODES_C + 255) / 256, 256>>>();
    detect_dtype_kernel<<<256, 256>>>(ei32);
    decode_hist_kernel<<<(N_EDGES_C + 255) / 256, 256>>>(ei32);
    scan_blocksum_kernel<<<SCAN_BLOCKS, 256>>>();
    scan_toplevel_kernel<<<1, 256>>>();
    scan_write_kernel<<<SCAN_BLOCKS, 256>>>();
    bucket_kernel<<<(N_EDGES_C + 255) / 256, 256>>>();

    gemm_bias_relu_kernel<<<N_NODES_C / 64, 256>>>(x, w, bias, h);

    aggregate_kernel<<<(N_NODES_C * 32 + 255) / 256, 256>>>(h, out);
}